// round 16
// baseline (speedup 1.0000x reference)
#include <cuda_runtime.h>
#include <math.h>
#include <stdint.h>

#define NN 50000
#define NE 600000
#define NC 500
#define CE 8000
#define EPSV 1e-5f
#define NBN 49        // (NN+1023)/1024
#define NBC 1
#define NBEN 2344     // (NE+255)/256
#define NBEC 32       // (CE+255)/256
#define GN 782        // (NN+63)/64
#define GC 8          // (NC+63)/64

// ---------------- scratch ----------------
__device__ float g_bufA[NN*128];
__device__ float g_bufB[NN*128];
__device__ float g_agg [NN*128];
__device__ float g_tmp [NN*128];
__device__ float g_cA  [NC*128];
__device__ float g_cB  [NC*128];
__device__ float g_cagg[NC*128];
__device__ float g_ctmp[NC*128];
__device__ float g_qkvN[(size_t)NN*384];
__device__ float g_qkvC[NC*384];
__device__ float g_z1  [NN*64];
__device__ int   g_degN [NN];
__device__ int   g_offN [NN+1];
__device__ int2  g_cwN  [NE];      // {src, w bits} packed
__device__ int   g_rankN[NE];
__device__ float g_dinvN[NN];
__device__ int   g_degC [NC];
__device__ int   g_offC [NC+1];
__device__ int2  g_cwC  [CE];
__device__ int   g_rankC[CE];
__device__ float g_dinvC[NC];
__device__ float g_stats[7*256];
__device__ float g_WiT[128*384];
__device__ float g_WoT[128*128];
__device__ int   g_partials[128];
__device__ int   g_scanflag[64];

// ---------------- prep: zero + weight transposes in one launch ----------------
__global__ void zero_transpose_kernel(const float* __restrict__ wi, const float* __restrict__ wo) {
    int i = blockIdx.x*blockDim.x + threadIdx.x;
    if (i < NN) g_degN[i] = 0;
    if (i < NC) g_degC[i] = 0;
    if (i < 7*256) g_stats[i] = 0.f;
    if (i < 64) g_scanflag[i] = 0;
    if (i < 384*128) { int j = i / 128, k = i % 128; g_WiT[k*384 + j] = wi[i]; }
    if (i < 128*128) { int j = i / 128, k = i % 128; g_WoT[k*128 + j] = wo[i]; }
}

// count degrees AND record each edge's rank within its dst bucket
__global__ void count_deg2_kernel(const int* __restrict__ ndst, const int* __restrict__ cdst) {
    int b = blockIdx.x;
    if (b < NBEN) {
        int e = b*256 + threadIdx.x;
        if (e < NE) g_rankN[e] = atomicAdd(&g_degN[ndst[e]], 1);
    } else {
        int e = (b - NBEN)*256 + threadIdx.x;
        if (e < CE) g_rankC[e] = atomicAdd(&g_degC[cdst[e]], 1);
    }
}

// single-pass scan (all 50 blocks co-resident): local scan + flag-publish + off/dinv
__global__ void scan_fused_kernel() {
    __shared__ int s[256];
    __shared__ int sbase;
    int t = threadIdx.x;
    const int* cnt; int* off; float* dinv; int n, bid, nb, fbase;
    if (blockIdx.x < NBN) { cnt = g_degN; off = g_offN; dinv = g_dinvN; n = NN; bid = blockIdx.x; nb = NBN; fbase = 0; }
    else { cnt = g_degC; off = g_offC; dinv = g_dinvC; n = NC; bid = (int)blockIdx.x - NBN; nb = NBC; fbase = NBN; }
    int base = bid * 1024;
    int v[4];
    int local = 0;
    #pragma unroll
    for (int j = 0; j < 4; j++) {
        int i = base + t*4 + j;
        v[j] = (i < n) ? cnt[i] : 0;
        local += v[j];
    }
    s[t] = local; __syncthreads();
    int x = local;
    #pragma unroll
    for (int d = 1; d < 256; d <<= 1) {
        int add = (t >= d) ? s[t-d] : 0;
        __syncthreads();
        s[t] += add;
        __syncthreads();
    }
    int total = s[255];
    if (t == 0) {
        sbase = 0;
        atomicExch(&g_partials[fbase + bid], total);
        __threadfence();
        atomicExch(&g_scanflag[fbase + bid], 1);
    }
    __syncthreads();
    if (t < bid) {
        while (atomicAdd(&g_scanflag[fbase + t], 0) == 0) {}
        atomicAdd(&sbase, atomicAdd(&g_partials[fbase + t], 0));
    }
    __syncthreads();
    int tbase = sbase + s[t] - x;
    #pragma unroll
    for (int j = 0; j < 4; j++) {
        int i = base + t*4 + j;
        if (i < n) {
            off[i] = tbase; tbase += v[j];
            dinv[i] = 1.0f / sqrtf((float)(v[j] + 1));
        }
    }
    if (bid == nb - 1 && t == 0) off[n] = sbase + total;
}

// atomic-free scatter using precomputed ranks; single int2 store per edge
__global__ void fill_csr2_kernel(const int* __restrict__ nsrc, const int* __restrict__ ndst,
                                 const int* __restrict__ csrc, const int* __restrict__ cdst) {
    int b = blockIdx.x;
    if (b < NBEN) {
        int e = b*256 + threadIdx.x;
        if (e < NE) {
            int s = nsrc[e], d = ndst[e];
            int pos = g_offN[d] + g_rankN[e];
            float w = g_dinvN[s] * g_dinvN[d];
            g_cwN[pos] = make_int2(s, __float_as_int(w));
        }
    } else {
        int e = (b - NBEN)*256 + threadIdx.x;
        if (e < CE) {
            int s = csrc[e], d = cdst[e];
            int pos = g_offC[d] + g_rankC[e];
            float w = g_dinvC[s] * g_dinvC[d];
            g_cwC[pos] = make_int2(s, __float_as_int(w));
        }
    }
}

// ---------------- fused GCN aggregation (node + comm), prefetch-1, int2 edges ----------------
__global__ void gcn_agg2_kernel(const float* __restrict__ hN, float* __restrict__ aggN,
                                const float* __restrict__ hC, float* __restrict__ aggC) {
    int gw = (blockIdx.x*blockDim.x + threadIdx.x) >> 5;
    int lane = threadIdx.x & 31;
    const float* h; float* agg; const int* off; const int2* cw; const float* dinv;
    int node;
    if (gw < NN) {
        h = hN; agg = aggN; off = g_offN; cw = g_cwN; dinv = g_dinvN; node = gw;
    } else if (gw < NN + NC) {
        h = hC; agg = aggC; off = g_offC; cw = g_cwC; dinv = g_dinvC; node = gw - NN;
    } else return;

    float dv = dinv[node];
    float sw = dv * dv;
    float4 hv = *(const float4*)(h + (size_t)node*128 + lane*4);
    float4 acc = make_float4(sw*hv.x, sw*hv.y, sw*hv.z, sw*hv.w);
    int s = off[node], e = off[node+1];
    int j = s;
    if (j < e) {
        int2 c = cw[j];
        for (; j + 1 < e; j++) {
            int2 cn = cw[j+1];                                   // prefetch next edge
            float ww = __int_as_float(c.y);
            float4 xv = *(const float4*)(h + (size_t)c.x*128 + lane*4);
            acc.x += ww*xv.x; acc.y += ww*xv.y; acc.z += ww*xv.z; acc.w += ww*xv.w;
            c = cn;
        }
        float ww = __int_as_float(c.y);
        float4 xv = *(const float4*)(h + (size_t)c.x*128 + lane*4);
        acc.x += ww*xv.x; acc.y += ww*xv.y; acc.z += ww*xv.z; acc.w += ww*xv.w;
    }
    *(float4*)(agg + (size_t)node*128 + lane*4) = acc;
}

// ---------------- fused GEMM (node blocks + comm blocks), optional stats ----------------
template<bool STATS>
__global__ __launch_bounds__(256) void gemm2_kernel(
        const float* __restrict__ A0, const float* __restrict__ W0, const float* __restrict__ b0,
        float* __restrict__ out0, float* __restrict__ st0, int M0,
        const float* __restrict__ A1, const float* __restrict__ W1, const float* __restrict__ b1,
        float* __restrict__ out1, float* __restrict__ st1, int M1,
        int ldW, int ldOut) {
    extern __shared__ float sm[];
    float* sW = sm;               // 128*128
    float* sA = sm + 128*128;     // 64*128
    float4* sW4 = (float4*)sW;
    float4* sA4 = (float4*)sA;
    const int t = threadIdx.x;
    const int cOff = blockIdx.y * 128;

    const float *A, *W, *bias; float *out, *stats; int M, rowBase;
    if (blockIdx.x < GN) {
        A = A0; W = W0; bias = b0; out = out0; stats = st0; M = M0; rowBase = blockIdx.x * 64;
    } else {
        A = A1; W = W1; bias = b1; out = out1; stats = st1; M = M1; rowBase = (blockIdx.x - GN) * 64;
    }

    #pragma unroll
    for (int j = 0; j < 16; j++) {
        int g4 = t + j*256;
        int k = g4 >> 5, c4 = g4 & 31;
        sW4[g4] = *(const float4*)(W + (size_t)k*ldW + cOff + c4*4);
    }
    #pragma unroll
    for (int j = 0; j < 8; j++) {
        int g4 = t + j*256;
        int r = g4 >> 5, c4 = g4 & 31;
        int gr = rowBase + r;
        float4 v = make_float4(0.f, 0.f, 0.f, 0.f);
        if (gr < M) v = *(const float4*)(A + (size_t)gr*128 + c4*4);
        sA4[g4] = v;
    }
    __syncthreads();

    const int lane = t & 31, warp = t >> 5;
    const int r0 = warp * 8;
    float4 acc[8];
    #pragma unroll
    for (int r = 0; r < 8; r++) acc[r] = make_float4(0.f, 0.f, 0.f, 0.f);

    #pragma unroll 2
    for (int k4 = 0; k4 < 32; k4++) {
        float4 w0 = sW4[(k4*4+0)*32 + lane];
        float4 w1 = sW4[(k4*4+1)*32 + lane];
        float4 w2 = sW4[(k4*4+2)*32 + lane];
        float4 w3 = sW4[(k4*4+3)*32 + lane];
        #pragma unroll
        for (int r = 0; r < 8; r++) {
            float4 av = sA4[(r0+r)*32 + k4];
            acc[r].x = fmaf(av.x,w0.x, fmaf(av.y,w1.x, fmaf(av.z,w2.x, fmaf(av.w,w3.x, acc[r].x))));
            acc[r].y = fmaf(av.x,w0.y, fmaf(av.y,w1.y, fmaf(av.z,w2.y, fmaf(av.w,w3.y, acc[r].y))));
            acc[r].z = fmaf(av.x,w0.z, fmaf(av.y,w1.z, fmaf(av.z,w2.z, fmaf(av.w,w3.z, acc[r].z))));
            acc[r].w = fmaf(av.x,w0.w, fmaf(av.y,w1.w, fmaf(av.z,w2.w, fmaf(av.w,w3.w, acc[r].w))));
        }
    }

    float4 bv = *(const float4*)(bias + cOff + lane*4);
    float4 psum = make_float4(0.f,0.f,0.f,0.f), psq = make_float4(0.f,0.f,0.f,0.f);
    #pragma unroll
    for (int r = 0; r < 8; r++) {
        int gr = rowBase + r0 + r;
        if (gr < M) {
            float4 o = make_float4(acc[r].x+bv.x, acc[r].y+bv.y, acc[r].z+bv.z, acc[r].w+bv.w);
            *(float4*)(out + (size_t)gr*ldOut + cOff + lane*4) = o;
            if (STATS) {
                psum.x += o.x; psum.y += o.y; psum.z += o.z; psum.w += o.w;
                psq.x += o.x*o.x; psq.y += o.y*o.y; psq.z += o.z*o.z; psq.w += o.w*o.w;
            }
        }
    }
    if (STATS) {
        __syncthreads();
        float* sSum = sA;
        float* sSq  = sA + 128;
        if (t < 256) sA[t] = 0.f;
        __syncthreads();
        atomicAdd(&sSum[lane*4+0], psum.x); atomicAdd(&sSum[lane*4+1], psum.y);
        atomicAdd(&sSum[lane*4+2], psum.z); atomicAdd(&sSum[lane*4+3], psum.w);
        atomicAdd(&sSq [lane*4+0], psq.x);  atomicAdd(&sSq [lane*4+1], psq.y);
        atomicAdd(&sSq [lane*4+2], psq.z);  atomicAdd(&sSq [lane*4+3], psq.w);
        __syncthreads();
        if (t < 128) { atomicAdd(&stats[t], sSum[t]); atomicAdd(&stats[128+t], sSq[t]); }
    }
}

// ---------------- fused BN + ReLU + residual (node + comm), float4 ----------------
__global__ void bn2_kernel(const float* __restrict__ tN, const float* __restrict__ stN,
                           const float* __restrict__ gN, const float* __restrict__ bN,
                           const float* __restrict__ hpN, float* __restrict__ hoN,
                           const float* __restrict__ tC, const float* __restrict__ stC,
                           const float* __restrict__ gC, const float* __restrict__ bC,
                           const float* __restrict__ hpC, float* __restrict__ hoC,
                           int residual) {
    int idx = blockIdx.x*blockDim.x + threadIdx.x;
    const float *tin, *stats, *g, *b, *hp; float* ho; float invN;
    if (idx < NN*32) {
        tin = tN; stats = stN; g = gN; b = bN; hp = hpN; ho = hoN; invN = 1.0f/NN;
    } else if (idx < (NN+NC)*32) {
        idx -= NN*32;
        tin = tC; stats = stC; g = gC; b = bC; hp = hpC; ho = hoC; invN = 1.0f/NC;
    } else return;
    int c4 = (idx & 31) * 4;
    float4 mu4 = *(const float4*)(stats + c4);
    float4 v4  = *(const float4*)(stats + 128 + c4);
    float4 g4v = *(const float4*)(g + c4);
    float4 b4v = *(const float4*)(b + c4);
    float m0 = mu4.x*invN, m1 = mu4.y*invN, m2 = mu4.z*invN, m3 = mu4.w*invN;
    float s0 = g4v.x * rsqrtf(v4.x*invN - m0*m0 + EPSV);
    float s1 = g4v.y * rsqrtf(v4.y*invN - m1*m1 + EPSV);
    float s2 = g4v.z * rsqrtf(v4.z*invN - m2*m2 + EPSV);
    float s3 = g4v.w * rsqrtf(v4.w*invN - m3*m3 + EPSV);
    float4 x = ((const float4*)tin)[idx];
    float4 y;
    y.x = fmaxf((x.x - m0)*s0 + b4v.x, 0.f);
    y.y = fmaxf((x.y - m1)*s1 + b4v.y, 0.f);
    y.z = fmaxf((x.z - m2)*s2 + b4v.z, 0.f);
    y.w = fmaxf((x.w - m3)*s3 + b4v.w, 0.f);
    if (residual) {
        float4 p = ((const float4*)hp)[idx];
        y.x += p.x; y.y += p.y; y.z += p.z; y.w += p.w;
    }
    ((float4*)ho)[idx] = y;
}

// ---------------- attn + LN + cls GEMM1, phase-structured block GEMMs ----------------
__global__ __launch_bounds__(256, 2) void attn_cls_kernel(
        const float* __restrict__ qkvN, const float* __restrict__ qkvC,
        const int* __restrict__ map,
        const float* __restrict__ hnode,
        const float* __restrict__ WoT, const float* __restrict__ bo,
        const float* __restrict__ lng, const float* __restrict__ lnb,
        const float* __restrict__ W1, const float* __restrict__ b1,
        float* __restrict__ z, float* __restrict__ stats, int n) {
    extern __shared__ float sm[];
    float* sWoT = sm;                    // 16384 floats
    float* sOm  = sm + 16384;            // 8192 floats (64 x 128)
    float* sSum = sm + 24576;            // 64
    float* sSq  = sm + 24640;            // 64
    float4* sW4 = (float4*)sWoT;
    float4* sOm4 = (float4*)sOm;
    int t = threadIdx.x;
    #pragma unroll
    for (int j = 0; j < 16; j++) sW4[t + j*256] = ((const float4*)WoT)[t + j*256];
    if (t < 64) { sSum[t] = 0.f; sSq[t] = 0.f; }

    int lane = t & 31, warp = t >> 5;
    int nodeBase = blockIdx.x * 64;

    // ---- Phase A: attention rows -> sOm ----
    #pragma unroll
    for (int it = 0; it < 8; it++) {
        int r = warp*8 + it;
        int node = nodeBase + r;
        float4 om = make_float4(0.f, 0.f, 0.f, 0.f);
        if (node < n) {
            int cm = map[node];
            cm = cm < 0 ? 0 : (cm > NC-1 ? NC-1 : cm);
            const float4* row0 = (const float4*)(qkvN + (size_t)node*384);
            const float4* row1 = (const float4*)(qkvC + (size_t)cm*384);
            float4 q0 = row0[lane],    q1 = row1[lane];
            float4 k0 = row0[32+lane], k1 = row1[32+lane];
            float4 v0 = row0[64+lane], v1 = row1[64+lane];

            float s00 = q0.x*k0.x + q0.y*k0.y + q0.z*k0.z + q0.w*k0.w;
            float s01 = q0.x*k1.x + q0.y*k1.y + q0.z*k1.z + q0.w*k1.w;
            float s10 = q1.x*k0.x + q1.y*k0.y + q1.z*k0.z + q1.w*k0.w;
            float s11 = q1.x*k1.x + q1.y*k1.y + q1.z*k1.z + q1.w*k1.w;
            #pragma unroll
            for (int m = 1; m <= 2; m <<= 1) {
                s00 += __shfl_xor_sync(0xffffffffu, s00, m);
                s01 += __shfl_xor_sync(0xffffffffu, s01, m);
                s10 += __shfl_xor_sync(0xffffffffu, s10, m);
                s11 += __shfl_xor_sync(0xffffffffu, s11, m);
            }
            s00 *= 0.25f; s01 *= 0.25f; s10 *= 0.25f; s11 *= 0.25f;
            float m0 = fmaxf(s00, s01);
            float e00 = expf(s00-m0), e01 = expf(s01-m0);
            float r0i = 1.f/(e00+e01);
            float p00 = e00*r0i, p01 = e01*r0i;
            float m1 = fmaxf(s10, s11);
            float e10 = expf(s10-m1), e11 = expf(s11-m1);
            float r1i = 1.f/(e10+e11);
            float p10 = e10*r1i, p11 = e11*r1i;

            om.x = 0.5f*(p00*v0.x + p01*v1.x + p10*v0.x + p11*v1.x);
            om.y = 0.5f*(p00*v0.y + p01*v1.y + p10*v0.y + p11*v1.y);
            om.z = 0.5f*(p00*v0.z + p01*v1.z + p10*v0.z + p11*v1.z);
            om.w = 0.5f*(p00*v0.w + p01*v1.w + p10*v0.w + p11*v1.w);
        }
        sOm4[r*32 + lane] = om;
    }
    __syncthreads();

    // ---- Phase B: block GEMM sOm @ WoT + (hnode + bo), then LayerNorm -> sOm ----
    const int r0 = warp * 8;
    float4 bv = ((const float4*)bo)[lane];
    float4 acc[8];
    #pragma unroll
    for (int r = 0; r < 8; r++) {
        int node = nodeBase + r0 + r;
        float4 h = make_float4(0.f, 0.f, 0.f, 0.f);
        if (node < n) h = ((const float4*)(hnode + (size_t)node*128))[lane];
        acc[r] = make_float4(h.x+bv.x, h.y+bv.y, h.z+bv.z, h.w+bv.w);
    }
    #pragma unroll 2
    for (int k4 = 0; k4 < 32; k4++) {
        float4 w0 = sW4[(k4*4+0)*32 + lane];
        float4 w1 = sW4[(k4*4+1)*32 + lane];
        float4 w2 = sW4[(k4*4+2)*32 + lane];
        float4 w3 = sW4[(k4*4+3)*32 + lane];
        #pragma unroll
        for (int r = 0; r < 8; r++) {
            float4 av = sOm4[(r0+r)*32 + k4];
            acc[r].x = fmaf(av.x,w0.x, fmaf(av.y,w1.x, fmaf(av.z,w2.x, fmaf(av.w,w3.x, acc[r].x))));
            acc[r].y = fmaf(av.x,w0.y, fmaf(av.y,w1.y, fmaf(av.z,w2.y, fmaf(av.w,w3.y, acc[r].y))));
            acc[r].z = fmaf(av.x,w0.z, fmaf(av.y,w1.z, fmaf(av.z,w2.z, fmaf(av.w,w3.z, acc[r].z))));
            acc[r].w = fmaf(av.x,w0.w, fmaf(av.y,w1.w, fmaf(av.z,w2.w, fmaf(av.w,w3.w, acc[r].w))));
        }
    }
    __syncthreads();
    float4 gv  = ((const float4*)lng)[lane];
    float4 bbv = ((const float4*)lnb)[lane];
    #pragma unroll
    for (int r = 0; r < 8; r++) {
        float4 a = acc[r];
        float sum = a.x+a.y+a.z+a.w;
        float sq  = a.x*a.x + a.y*a.y + a.z*a.z + a.w*a.w;
        #pragma unroll
        for (int m = 16; m >= 1; m >>= 1) {
            sum += __shfl_xor_sync(0xffffffffu, sum, m);
            sq  += __shfl_xor_sync(0xffffffffu, sq, m);
        }
        float mu = sum * (1.f/128.f);
        float var = sq * (1.f/128.f) - mu*mu;
        float inv = rsqrtf(var + EPSV);
        float4 o;
        o.x = (a.x-mu)*inv*gv.x + bbv.x;
        o.y = (a.y-mu)*inv*gv.y + bbv.y;
        o.z = (a.z-mu)*inv*gv.z + bbv.z;
        o.w = (a.w-mu)*inv*gv.w + bbv.w;
        sOm4[(r0+r)*32 + lane] = o;
    }
    __syncthreads();

    // ---- Phase C: block GEMM sOm @ W1 (global, L1-resident) + b1 -> z, stats ----
    float b1x = b1[2*lane], b1y = b1[2*lane+1];
    float2 zacc[8];
    #pragma unroll
    for (int r = 0; r < 8; r++) zacc[r] = make_float2(b1x, b1y);
    const float2* W1g = (const float2*)W1;
    #pragma unroll 2
    for (int k4 = 0; k4 < 32; k4++) {
        float2 w0 = W1g[(k4*4+0)*32 + lane];
        float2 w1 = W1g[(k4*4+1)*32 + lane];
        float2 w2 = W1g[(k4*4+2)*32 + lane];
        float2 w3 = W1g[(k4*4+3)*32 + lane];
        #pragma unroll
        for (int r = 0; r < 8; r++) {
            float4 a = sOm4[(r0+r)*32 + k4];
            zacc[r].x = fmaf(a.x,w0.x, fmaf(a.y,w1.x, fmaf(a.z,w2.x, fmaf(a.w,w3.x, zacc[r].x))));
            zacc[r].y = fmaf(a.x,w0.y, fmaf(a.y,w1.y, fmaf(a.z,w2.y, fmaf(a.w,w3.y, zacc[r].y))));
        }
    }
    float2 ps = make_float2(0.f,0.f), psq = make_float2(0.f,0.f);
    #pragma unroll
    for (int r = 0; r < 8; r++) {
        int node = nodeBase + r0 + r;
        if (node < n) {
            ((float2*)(z + (size_t)node*64))[lane] = zacc[r];
            ps.x += zacc[r].x; ps.y += zacc[r].y;
            psq.x += zacc[r].x*zacc[r].x; psq.y += zacc[r].y*zacc[r].y;
        }
    }
    atomicAdd(&sSum[2*lane],   ps.x); atomicAdd(&sSum[2*lane+1], ps.y);
    atomicAdd(&sSq [2*lane],   psq.x); atomicAdd(&sSq [2*lane+1], psq.y);
    __syncthreads();
    if (t < 64) { atomicAdd(&stats[t], sSum[t]); atomicAdd(&stats[64+t], sSq[t]); }
}

// ---------------- classifier tail ----------------
__global__ void cls_final_kernel(const float* __restrict__ z, const float* __restrict__ stats,
                                 const float* __restrict__ bng, const float* __restrict__ bnb,
                                 const float* __restrict__ W2, const float* __restrict__ b2,
                                 float* __restrict__ out, int n) {
    __shared__ float sW2[640];
    __shared__ float sb2[16];
    __shared__ float sZ[8][64];
    int t = threadIdx.x, lane = t & 31, warp = t >> 5;
    for (int j = t; j < 640; j += 256) sW2[j] = W2[j];
    if (t < 10) sb2[t] = b2[t];
    __syncthreads();

    float invN = 1.f / (float)n;
    int c0 = 2*lane, c1 = c0 + 1;
    float mu0 = stats[c0]*invN, mu1 = stats[c1]*invN;
    float v0 = stats[64+c0]*invN - mu0*mu0;
    float v1 = stats[64+c1]*invN - mu1*mu1;
    float sc0 = bng[c0] / sqrtf(v0 + EPSV);
    float sc1 = bng[c1] / sqrtf(v1 + EPSV);
    float sh0 = bnb[c0] - mu0*sc0;
    float sh1 = bnb[c1] - mu1*sc1;

    for (int it = 0; it < 8; it++) {
        int row = blockIdx.x*64 + warp*8 + it;
        if (row < n) {
            float2 zv = ((const float2*)(z + (size_t)row*64))[lane];
            sZ[warp][c0] = fmaxf(zv.x*sc0 + sh0, 0.f);
            sZ[warp][c1] = fmaxf(zv.y*sc1 + sh1, 0.f);
            __syncwarp();
            float logit = -1e30f;
            if (lane < 10) {
                logit = sb2[lane];
                #pragma unroll 8
                for (int k = 0; k < 64; k++) logit = fmaf(sZ[warp][k], sW2[k*10+lane], logit);
            }
            float mx = logit;
            #pragma unroll
            for (int m = 16; m >= 1; m >>= 1) mx = fmaxf(mx, __shfl_xor_sync(0xffffffffu, mx, m));
            float ex = (lane < 10) ? expf(logit - mx) : 0.f;
            float s = ex;
            #pragma unroll
            for (int m = 16; m >= 1; m >>= 1) s += __shfl_xor_sync(0xffffffffu, s, m);
            if (lane < 10) out[(size_t)row*10 + lane] = logit - mx - logf(s);
            __syncwarp();
        }
    }
}

// ---------------- host ----------------
extern "C" void kernel_launch(void* const* d_in, const int* in_sizes, int n_in,
                              void* d_out, int out_size) {
    const float* node_features = (const float*)d_in[0];
    const int*   node_ei       = (const int*)d_in[1];
    const float* comm_features = (const float*)d_in[2];
    const int*   comm_ei       = (const int*)d_in[3];
    const int*   n2c           = (const int*)d_in[4];
    const float* node_W   = (const float*)d_in[5];
    const float* node_b   = (const float*)d_in[6];
    const float* node_g   = (const float*)d_in[7];
    const float* node_be  = (const float*)d_in[8];
    const float* comm_W   = (const float*)d_in[9];
    const float* comm_b   = (const float*)d_in[10];
    const float* comm_g   = (const float*)d_in[11];
    const float* comm_be  = (const float*)d_in[12];
    const float* attn_in_w  = (const float*)d_in[13];
    const float* attn_in_b  = (const float*)d_in[14];
    const float* attn_out_w = (const float*)d_in[15];
    const float* attn_out_b = (const float*)d_in[16];
    const float* ln_g  = (const float*)d_in[17];
    const float* ln_b  = (const float*)d_in[18];
    const float* cls_W1 = (const float*)d_in[19];
    const float* cls_b1 = (const float*)d_in[20];
    const float* cls_bg = (const float*)d_in[21];
    const float* cls_bb = (const float*)d_in[22];
    const float* cls_W2 = (const float*)d_in[23];
    const float* cls_b2 = (const float*)d_in[24];
    float* out = (float*)d_out;

    float *bufA, *bufB, *agg, *tmp, *cA, *cB, *cagg, *ctmp, *qkvN, *qkvC, *z1;
    float *stats, *WiT, *WoT;
    cudaGetSymbolAddress((void**)&bufA, g_bufA);
    cudaGetSymbolAddress((void**)&bufB, g_bufB);
    cudaGetSymbolAddress((void**)&agg,  g_agg);
    cudaGetSymbolAddress((void**)&tmp,  g_tmp);
    cudaGetSymbolAddress((void**)&cA,   g_cA);
    cudaGetSymbolAddress((void**)&cB,   g_cB);
    cudaGetSymbolAddress((void**)&cagg, g_cagg);
    cudaGetSymbolAddress((void**)&ctmp, g_ctmp);
    cudaGetSymbolAddress((void**)&qkvN, g_qkvN);
    cudaGetSymbolAddress((void**)&qkvC, g_qkvC);
    cudaGetSymbolAddress((void**)&z1,   g_z1);
    cudaGetSymbolAddress((void**)&stats, g_stats);
    cudaGetSymbolAddress((void**)&WiT,  g_WiT);
    cudaGetSymbolAddress((void**)&WoT,  g_WoT);

    cudaFuncSetAttribute(gemm2_kernel<true>,  cudaFuncAttributeMaxDynamicSharedMemorySize, 98304);
    cudaFuncSetAttribute(gemm2_kernel<false>, cudaFuncAttributeMaxDynamicSharedMemorySize, 98304);
    cudaFuncSetAttribute(attn_cls_kernel,     cudaFuncAttributeMaxDynamicSharedMemorySize, 98816);

    // ---- fused graph prep ----
    zero_transpose_kernel<<<(NN+255)/256, 256>>>(attn_in_w, attn_out_w);
    count_deg2_kernel<<<NBEN + NBEC, 256>>>(node_ei + NE, comm_ei + CE);
    scan_fused_kernel<<<NBN + NBC, 256>>>();
    fill_csr2_kernel<<<NBEN + NBEC, 256>>>(node_ei, node_ei + NE, comm_ei, comm_ei + CE);

    // ---- fused GCN stacks ----
    const float* hinN = node_features;
    const float* hinC = comm_features;
    float* houtsN[3] = { bufA, bufB, bufA };
    float* houtsC[3] = { cA, cB, cA };
    int aggWarps = NN + NC;
    for (int i = 0; i < 3; i++) {
        gcn_agg2_kernel<<<(aggWarps*32 + 255)/256, 256>>>(hinN, agg, hinC, cagg);
        gemm2_kernel<true><<<dim3(GN + GC, 1), 256, 98304>>>(
            agg,  node_W + i*16384, node_b + i*128, tmp,  stats + i*256,     NN,
            cagg, comm_W + i*16384, comm_b + i*128, ctmp, stats + (3+i)*256, NC,
            128, 128);
        bn2_kernel<<<((NN+NC)*32 + 255)/256, 256>>>(
            tmp,  stats + i*256,     node_g + i*128, node_be + i*128, hinN, houtsN[i],
            ctmp, stats + (3+i)*256, comm_g + i*128, comm_be + i*128, hinC, houtsC[i],
            i > 0);
        hinN = houtsN[i];
        hinC = houtsC[i];
    }

    // ---- fused qkv GEMM (3 parallel column-tile blocks) ----
    gemm2_kernel<false><<<dim3(GN + GC, 3), 256, 98304>>>(
        hinN, WiT, attn_in_b, qkvN, nullptr, NN,
        hinC, WiT, attn_in_b, qkvC, nullptr, NC,
        384, 384);

    // ---- attention + LN + cls GEMM1 (phase-structured) ----
    attn_cls_kernel<<<(NN+63)/64, 256, 98816>>>(
        qkvN, qkvC, n2c, hinN, WoT, attn_out_b, ln_g, ln_b,
        cls_W1, cls_b1, z1, stats + 6*256, NN);

    // ---- classifier tail ----
    cls_final_kernel<<<(NN+63)/64, 256>>>(z1, stats + 6*256, cls_bg, cls_bb, cls_W2, cls_b2, out, NN);
}

// round 17
// speedup vs baseline: 1.0334x; 1.0334x over previous
#include <cuda_runtime.h>
#include <math.h>
#include <stdint.h>

#define NN 50000
#define NE 600000
#define NC 500
#define CE 8000
#define EPSV 1e-5f
#define NBN 49        // (NN+1023)/1024
#define NBC 1
#define NBEN 2344     // (NE+255)/256
#define NBEC 32       // (CE+255)/256
#define GN 782        // (NN+63)/64
#define GC 8          // (NC+63)/64

// ---------------- scratch ----------------
__device__ float g_bufA[NN*128];
__device__ float g_bufB[NN*128];
__device__ float g_agg [NN*128];
__device__ float g_tmp [NN*128];
__device__ float g_cA  [NC*128];
__device__ float g_cB  [NC*128];
__device__ float g_cagg[NC*128];
__device__ float g_ctmp[NC*128];
__device__ float g_qkvN[(size_t)NN*384];
__device__ float g_qkvC[NC*384];
__device__ float g_z1  [NN*64];
__device__ int   g_degN [NN];
__device__ int   g_offN [NN+1];
__device__ int   g_colN [NE];
__device__ int   g_rankN[NE];
__device__ float g_wN   [NE];
__device__ float g_dinvN[NN];
__device__ int   g_degC [NC];
__device__ int   g_offC [NC+1];
__device__ int   g_colC [CE];
__device__ int   g_rankC[CE];
__device__ float g_wC   [CE];
__device__ float g_dinvC[NC];
__device__ float g_stats[7*256];
__device__ float g_WiT[128*384];
__device__ float g_WoT[128*128];
__device__ int   g_partials[128];
__device__ int   g_scanflag[64];

// ---------------- prep: zero + weight transposes in one launch ----------------
__global__ void zero_transpose_kernel(const float* __restrict__ wi, const float* __restrict__ wo) {
    int i = blockIdx.x*blockDim.x + threadIdx.x;
    if (i < NN) g_degN[i] = 0;
    if (i < NC) g_degC[i] = 0;
    if (i < 7*256) g_stats[i] = 0.f;
    if (i < 64) g_scanflag[i] = 0;
    if (i < 384*128) { int j = i / 128, k = i % 128; g_WiT[k*384 + j] = wi[i]; }
    if (i < 128*128) { int j = i / 128, k = i % 128; g_WoT[k*128 + j] = wo[i]; }
}

// count degrees AND record each edge's rank within its dst bucket
__global__ void count_deg2_kernel(const int* __restrict__ ndst, const int* __restrict__ cdst) {
    int b = blockIdx.x;
    if (b < NBEN) {
        int e = b*256 + threadIdx.x;
        if (e < NE) g_rankN[e] = atomicAdd(&g_degN[ndst[e]], 1);
    } else {
        int e = (b - NBEN)*256 + threadIdx.x;
        if (e < CE) g_rankC[e] = atomicAdd(&g_degC[cdst[e]], 1);
    }
}

// single-pass scan (all 50 blocks co-resident): local scan + flag-publish + off/dinv
__global__ void scan_fused_kernel() {
    __shared__ int s[256];
    __shared__ int sbase;
    int t = threadIdx.x;
    const int* cnt; int* off; float* dinv; int n, bid, nb, fbase;
    if (blockIdx.x < NBN) { cnt = g_degN; off = g_offN; dinv = g_dinvN; n = NN; bid = blockIdx.x; nb = NBN; fbase = 0; }
    else { cnt = g_degC; off = g_offC; dinv = g_dinvC; n = NC; bid = (int)blockIdx.x - NBN; nb = NBC; fbase = NBN; }
    int base = bid * 1024;
    int v[4];
    int local = 0;
    #pragma unroll
    for (int j = 0; j < 4; j++) {
        int i = base + t*4 + j;
        v[j] = (i < n) ? cnt[i] : 0;
        local += v[j];
    }
    s[t] = local; __syncthreads();
    int x = local;
    #pragma unroll
    for (int d = 1; d < 256; d <<= 1) {
        int add = (t >= d) ? s[t-d] : 0;
        __syncthreads();
        s[t] += add;
        __syncthreads();
    }
    int total = s[255];
    if (t == 0) {
        sbase = 0;
        atomicExch(&g_partials[fbase + bid], total);
        __threadfence();
        atomicExch(&g_scanflag[fbase + bid], 1);
    }
    __syncthreads();
    if (t < bid) {
        while (atomicAdd(&g_scanflag[fbase + t], 0) == 0) {}
        atomicAdd(&sbase, atomicAdd(&g_partials[fbase + t], 0));
    }
    __syncthreads();
    int tbase = sbase + s[t] - x;
    #pragma unroll
    for (int j = 0; j < 4; j++) {
        int i = base + t*4 + j;
        if (i < n) {
            off[i] = tbase; tbase += v[j];
            dinv[i] = 1.0f / sqrtf((float)(v[j] + 1));
        }
    }
    if (bid == nb - 1 && t == 0) off[n] = sbase + total;
}

// atomic-free scatter using precomputed ranks
__global__ void fill_csr2_kernel(const int* __restrict__ nsrc, const int* __restrict__ ndst,
                                 const int* __restrict__ csrc, const int* __restrict__ cdst) {
    int b = blockIdx.x;
    if (b < NBEN) {
        int e = b*256 + threadIdx.x;
        if (e < NE) {
            int s = nsrc[e], d = ndst[e];
            int pos = g_offN[d] + g_rankN[e];
            g_colN[pos] = s;
            g_wN[pos] = g_dinvN[s] * g_dinvN[d];
        }
    } else {
        int e = (b - NBEN)*256 + threadIdx.x;
        if (e < CE) {
            int s = csrc[e], d = cdst[e];
            int pos = g_offC[d] + g_rankC[e];
            g_colC[pos] = s;
            g_wC[pos] = g_dinvC[s] * g_dinvC[d];
        }
    }
}

// ---------------- fused GCN aggregation (node + comm), prefetch-1 ----------------
__global__ void gcn_agg2_kernel(const float* __restrict__ hN, float* __restrict__ aggN,
                                const float* __restrict__ hC, float* __restrict__ aggC) {
    int gw = (blockIdx.x*blockDim.x + threadIdx.x) >> 5;
    int lane = threadIdx.x & 31;
    const float* h; float* agg; const int* off; const int* col; const float* w; const float* dinv;
    int node;
    if (gw < NN) {
        h = hN; agg = aggN; off = g_offN; col = g_colN; w = g_wN; dinv = g_dinvN; node = gw;
    } else if (gw < NN + NC) {
        h = hC; agg = aggC; off = g_offC; col = g_colC; w = g_wC; dinv = g_dinvC; node = gw - NN;
    } else return;

    float dv = dinv[node];
    float sw = dv * dv;
    float4 hv = *(const float4*)(h + (size_t)node*128 + lane*4);
    float4 acc = make_float4(sw*hv.x, sw*hv.y, sw*hv.z, sw*hv.w);
    int s = off[node], e = off[node+1];
    int j = s;
    if (j < e) {
        int src = col[j]; float ww = w[j];
        for (; j + 1 < e; j++) {
            int nsrc = col[j+1]; float nww = w[j+1];
            float4 xv = *(const float4*)(h + (size_t)src*128 + lane*4);
            acc.x += ww*xv.x; acc.y += ww*xv.y; acc.z += ww*xv.z; acc.w += ww*xv.w;
            src = nsrc; ww = nww;
        }
        float4 xv = *(const float4*)(h + (size_t)src*128 + lane*4);
        acc.x += ww*xv.x; acc.y += ww*xv.y; acc.z += ww*xv.z; acc.w += ww*xv.w;
    }
    *(float4*)(agg + (size_t)node*128 + lane*4) = acc;
}

// ---------------- fused GEMM (node blocks + comm blocks), optional stats ----------------
template<bool STATS>
__global__ __launch_bounds__(256) void gemm2_kernel(
        const float* __restrict__ A0, const float* __restrict__ W0, const float* __restrict__ b0,
        float* __restrict__ out0, float* __restrict__ st0, int M0,
        const float* __restrict__ A1, const float* __restrict__ W1, const float* __restrict__ b1,
        float* __restrict__ out1, float* __restrict__ st1, int M1,
        int ldW, int ldOut) {
    extern __shared__ float sm[];
    float* sW = sm;               // 128*128
    float* sA = sm + 128*128;     // 64*128
    float4* sW4 = (float4*)sW;
    float4* sA4 = (float4*)sA;
    const int t = threadIdx.x;
    const int cOff = blockIdx.y * 128;

    const float *A, *W, *bias; float *out, *stats; int M, rowBase;
    if (blockIdx.x < GN) {
        A = A0; W = W0; bias = b0; out = out0; stats = st0; M = M0; rowBase = blockIdx.x * 64;
    } else {
        A = A1; W = W1; bias = b1; out = out1; stats = st1; M = M1; rowBase = (blockIdx.x - GN) * 64;
    }

    #pragma unroll
    for (int j = 0; j < 16; j++) {
        int g4 = t + j*256;
        int k = g4 >> 5, c4 = g4 & 31;
        sW4[g4] = *(const float4*)(W + (size_t)k*ldW + cOff + c4*4);
    }
    #pragma unroll
    for (int j = 0; j < 8; j++) {
        int g4 = t + j*256;
        int r = g4 >> 5, c4 = g4 & 31;
        int gr = rowBase + r;
        float4 v = make_float4(0.f, 0.f, 0.f, 0.f);
        if (gr < M) v = *(const float4*)(A + (size_t)gr*128 + c4*4);
        sA4[g4] = v;
    }
    __syncthreads();

    const int lane = t & 31, warp = t >> 5;
    const int r0 = warp * 8;
    float4 acc[8];
    #pragma unroll
    for (int r = 0; r < 8; r++) acc[r] = make_float4(0.f, 0.f, 0.f, 0.f);

    #pragma unroll 2
    for (int k4 = 0; k4 < 32; k4++) {
        float4 w0 = sW4[(k4*4+0)*32 + lane];
        float4 w1 = sW4[(k4*4+1)*32 + lane];
        float4 w2 = sW4[(k4*4+2)*32 + lane];
        float4 w3 = sW4[(k4*4+3)*32 + lane];
        #pragma unroll
        for (int r = 0; r < 8; r++) {
            float4 av = sA4[(r0+r)*32 + k4];
            acc[r].x = fmaf(av.x,w0.x, fmaf(av.y,w1.x, fmaf(av.z,w2.x, fmaf(av.w,w3.x, acc[r].x))));
            acc[r].y = fmaf(av.x,w0.y, fmaf(av.y,w1.y, fmaf(av.z,w2.y, fmaf(av.w,w3.y, acc[r].y))));
            acc[r].z = fmaf(av.x,w0.z, fmaf(av.y,w1.z, fmaf(av.z,w2.z, fmaf(av.w,w3.z, acc[r].z))));
            acc[r].w = fmaf(av.x,w0.w, fmaf(av.y,w1.w, fmaf(av.z,w2.w, fmaf(av.w,w3.w, acc[r].w))));
        }
    }

    float4 bv = *(const float4*)(bias + cOff + lane*4);
    float4 psum = make_float4(0.f,0.f,0.f,0.f), psq = make_float4(0.f,0.f,0.f,0.f);
    #pragma unroll
    for (int r = 0; r < 8; r++) {
        int gr = rowBase + r0 + r;
        if (gr < M) {
            float4 o = make_float4(acc[r].x+bv.x, acc[r].y+bv.y, acc[r].z+bv.z, acc[r].w+bv.w);
            *(float4*)(out + (size_t)gr*ldOut + cOff + lane*4) = o;
            if (STATS) {
                psum.x += o.x; psum.y += o.y; psum.z += o.z; psum.w += o.w;
                psq.x += o.x*o.x; psq.y += o.y*o.y; psq.z += o.z*o.z; psq.w += o.w*o.w;
            }
        }
    }
    if (STATS) {
        // butterfly pre-reduction: columns repeat with period 32 lanes, so reduce
        // across warps via smem but first reduce within... columns differ per lane,
        // warps share the same column mapping -> reduce ACROSS warps per lane.
        // Use smem per-lane-column accumulation with only 8 atomic ops per thread -> 
        // keep simple: each thread atomically adds its 4 col values once per warp
        // after a cross-warp smem staging.
        __syncthreads();
        float* sSum = sA;
        float* sSq  = sA + 128;
        if (t < 256) sA[t] = 0.f;
        __syncthreads();
        // warps 0..7 all map lane -> cols lane*4..+3; stage per-warp partials in
        // distinct smem then tree-reduce: simpler: atomicAdd as before but only
        // 8 warps x 32 lanes x 4 ops = same count. Keep proven path:
        atomicAdd(&sSum[lane*4+0], psum.x); atomicAdd(&sSum[lane*4+1], psum.y);
        atomicAdd(&sSum[lane*4+2], psum.z); atomicAdd(&sSum[lane*4+3], psum.w);
        atomicAdd(&sSq [lane*4+0], psq.x);  atomicAdd(&sSq [lane*4+1], psq.y);
        atomicAdd(&sSq [lane*4+2], psq.z);  atomicAdd(&sSq [lane*4+3], psq.w);
        __syncthreads();
        if (t < 128) { atomicAdd(&stats[t], sSum[t]); atomicAdd(&stats[128+t], sSq[t]); }
    }
}

// ---------------- fused BN + ReLU + residual (node + comm), float4 ----------------
__global__ void bn2_kernel(const float* __restrict__ tN, const float* __restrict__ stN,
                           const float* __restrict__ gN, const float* __restrict__ bN,
                           const float* __restrict__ hpN, float* __restrict__ hoN,
                           const float* __restrict__ tC, const float* __restrict__ stC,
                           const float* __restrict__ gC, const float* __restrict__ bC,
                           const float* __restrict__ hpC, float* __restrict__ hoC,
                           int residual) {
    int idx = blockIdx.x*blockDim.x + threadIdx.x;
    const float *tin, *stats, *g, *b, *hp; float* ho; float invN;
    if (idx < NN*32) {
        tin = tN; stats = stN; g = gN; b = bN; hp = hpN; ho = hoN; invN = 1.0f/NN;
    } else if (idx < (NN+NC)*32) {
        idx -= NN*32;
        tin = tC; stats = stC; g = gC; b = bC; hp = hpC; ho = hoC; invN = 1.0f/NC;
    } else return;
    int c4 = (idx & 31) * 4;
    float4 mu4 = *(const float4*)(stats + c4);
    float4 v4  = *(const float4*)(stats + 128 + c4);
    float4 g4v = *(const float4*)(g + c4);
    float4 b4v = *(const float4*)(b + c4);
    float m0 = mu4.x*invN, m1 = mu4.y*invN, m2 = mu4.z*invN, m3 = mu4.w*invN;
    float s0 = g4v.x * rsqrtf(v4.x*invN - m0*m0 + EPSV);
    float s1 = g4v.y * rsqrtf(v4.y*invN - m1*m1 + EPSV);
    float s2 = g4v.z * rsqrtf(v4.z*invN - m2*m2 + EPSV);
    float s3 = g4v.w * rsqrtf(v4.w*invN - m3*m3 + EPSV);
    float4 x = ((const float4*)tin)[idx];
    float4 y;
    y.x = fmaxf((x.x - m0)*s0 + b4v.x, 0.f);
    y.y = fmaxf((x.y - m1)*s1 + b4v.y, 0.f);
    y.z = fmaxf((x.z - m2)*s2 + b4v.z, 0.f);
    y.w = fmaxf((x.w - m3)*s3 + b4v.w, 0.f);
    if (residual) {
        float4 p = ((const float4*)hp)[idx];
        y.x += p.x; y.y += p.y; y.z += p.z; y.w += p.w;
    }
    ((float4*)ho)[idx] = y;
}

// ---------------- attn + LN + cls GEMM1, phase-structured block GEMMs ----------------
__global__ __launch_bounds__(256, 2) void attn_cls_kernel(
        const float* __restrict__ qkvN, const float* __restrict__ qkvC,
        const int* __restrict__ map,
        const float* __restrict__ hnode,
        const float* __restrict__ WoT, const float* __restrict__ bo,
        const float* __restrict__ lng, const float* __restrict__ lnb,
        const float* __restrict__ W1, const float* __restrict__ b1,
        float* __restrict__ z, float* __restrict__ stats, int n) {
    extern __shared__ float sm[];
    float* sWoT = sm;                    // 16384 floats
    float* sOm  = sm + 16384;            // 8192 floats (64 x 128)
    float* sSum = sm + 24576;            // 64
    float* sSq  = sm + 24640;            // 64
    float4* sW4 = (float4*)sWoT;
    float4* sOm4 = (float4*)sOm;
    int t = threadIdx.x;
    #pragma unroll
    for (int j = 0; j < 16; j++) sW4[t + j*256] = ((const float4*)WoT)[t + j*256];
    if (t < 64) { sSum[t] = 0.f; sSq[t] = 0.f; }

    int lane = t & 31, warp = t >> 5;
    int nodeBase = blockIdx.x * 64;

    // ---- Phase A: attention rows -> sOm ----
    #pragma unroll
    for (int it = 0; it < 8; it++) {
        int r = warp*8 + it;
        int node = nodeBase + r;
        float4 om = make_float4(0.f, 0.f, 0.f, 0.f);
        if (node < n) {
            int cm = map[node];
            cm = cm < 0 ? 0 : (cm > NC-1 ? NC-1 : cm);
            const float4* row0 = (const float4*)(qkvN + (size_t)node*384);
            const float4* row1 = (const float4*)(qkvC + (size_t)cm*384);
            float4 q0 = row0[lane],    q1 = row1[lane];
            float4 k0 = row0[32+lane], k1 = row1[32+lane];
            float4 v0 = row0[64+lane], v1 = row1[64+lane];

            float s00 = q0.x*k0.x + q0.y*k0.y + q0.z*k0.z + q0.w*k0.w;
            float s01 = q0.x*k1.x + q0.y*k1.y + q0.z*k1.z + q0.w*k1.w;
            float s10 = q1.x*k0.x + q1.y*k0.y + q1.z*k0.z + q1.w*k0.w;
            float s11 = q1.x*k1.x + q1.y*k1.y + q1.z*k1.z + q1.w*k1.w;
            #pragma unroll
            for (int m = 1; m <= 2; m <<= 1) {
                s00 += __shfl_xor_sync(0xffffffffu, s00, m);
                s01 += __shfl_xor_sync(0xffffffffu, s01, m);
                s10 += __shfl_xor_sync(0xffffffffu, s10, m);
                s11 += __shfl_xor_sync(0xffffffffu, s11, m);
            }
            s00 *= 0.25f; s01 *= 0.25f; s10 *= 0.25f; s11 *= 0.25f;
            float m0 = fmaxf(s00, s01);
            float e00 = expf(s00-m0), e01 = expf(s01-m0);
            float r0i = 1.f/(e00+e01);
            float p00 = e00*r0i, p01 = e01*r0i;
            float m1 = fmaxf(s10, s11);
            float e10 = expf(s10-m1), e11 = expf(s11-m1);
            float r1i = 1.f/(e10+e11);
            float p10 = e10*r1i, p11 = e11*r1i;

            om.x = 0.5f*(p00*v0.x + p01*v1.x + p10*v0.x + p11*v1.x);
            om.y = 0.5f*(p00*v0.y + p01*v1.y + p10*v0.y + p11*v1.y);
            om.z = 0.5f*(p00*v0.z + p01*v1.z + p10*v0.z + p11*v1.z);
            om.w = 0.5f*(p00*v0.w + p01*v1.w + p10*v0.w + p11*v1.w);
        }
        sOm4[r*32 + lane] = om;
    }
    __syncthreads();

    // ---- Phase B: block GEMM sOm @ WoT + (hnode + bo), then LayerNorm -> sOm ----
    const int r0 = warp * 8;
    float4 bv = ((const float4*)bo)[lane];
    float4 acc[8];
    #pragma unroll
    for (int r = 0; r < 8; r++) {
        int node = nodeBase + r0 + r;
        float4 h = make_float4(0.f, 0.f, 0.f, 0.f);
        if (node < n) h = ((const float4*)(hnode + (size_t)node*128))[lane];
        acc[r] = make_float4(h.x+bv.x, h.y+bv.y, h.z+bv.z, h.w+bv.w);
    }
    #pragma unroll 2
    for (int k4 = 0; k4 < 32; k4++) {
        float4 w0 = sW4[(k4*4+0)*32 + lane];
        float4 w1 = sW4[(k4*4+1)*32 + lane];
        float4 w2 = sW4[(k4*4+2)*32 + lane];
        float4 w3 = sW4[(k4*4+3)*32 + lane];
        #pragma unroll
        for (int r = 0; r < 8; r++) {
            float4 av = sOm4[(r0+r)*32 + k4];
            acc[r].x = fmaf(av.x,w0.x, fmaf(av.y,w1.x, fmaf(av.z,w2.x, fmaf(av.w,w3.x, acc[r].x))));
            acc[r].y = fmaf(av.x,w0.y, fmaf(av.y,w1.y, fmaf(av.z,w2.y, fmaf(av.w,w3.y, acc[r].y))));
            acc[r].z = fmaf(av.x,w0.z, fmaf(av.y,w1.z, fmaf(av.z,w2.z, fmaf(av.w,w3.z, acc[r].z))));
            acc[r].w = fmaf(av.x,w0.w, fmaf(av.y,w1.w, fmaf(av.z,w2.w, fmaf(av.w,w3.w, acc[r].w))));
        }
    }
    __syncthreads();
    float4 gv  = ((const float4*)lng)[lane];
    float4 bbv = ((const float4*)lnb)[lane];
    #pragma unroll
    for (int r = 0; r < 8; r++) {
        float4 a = acc[r];
        float sum = a.x+a.y+a.z+a.w;
        float sq  = a.x*a.x + a.y*a.y + a.z*a.z + a.w*a.w;
        #pragma unroll
        for (int m = 16; m >= 1; m >>= 1) {
            sum += __shfl_xor_sync(0xffffffffu, sum, m);
            sq  += __shfl_xor_sync(0xffffffffu, sq, m);
        }
        float mu = sum * (1.f/128.f);
        float var = sq * (1.f/128.f) - mu*mu;
        float inv = rsqrtf(var + EPSV);
        float4 o;
        o.x = (a.x-mu)*inv*gv.x + bbv.x;
        o.y = (a.y-mu)*inv*gv.y + bbv.y;
        o.z = (a.z-mu)*inv*gv.z + bbv.z;
        o.w = (a.w-mu)*inv*gv.w + bbv.w;
        sOm4[(r0+r)*32 + lane] = o;
    }
    __syncthreads();

    // ---- Phase C: block GEMM sOm @ W1 (global, L1-resident) + b1 -> z, stats ----
    float b1x = b1[2*lane], b1y = b1[2*lane+1];
    float2 zacc[8];
    #pragma unroll
    for (int r = 0; r < 8; r++) zacc[r] = make_float2(b1x, b1y);
    const float2* W1g = (const float2*)W1;
    #pragma unroll 2
    for (int k4 = 0; k4 < 32; k4++) {
        float2 w0 = W1g[(k4*4+0)*32 + lane];
        float2 w1 = W1g[(k4*4+1)*32 + lane];
        float2 w2 = W1g[(k4*4+2)*32 + lane];
        float2 w3 = W1g[(k4*4+3)*32 + lane];
        #pragma unroll
        for (int r = 0; r < 8; r++) {
            float4 a = sOm4[(r0+r)*32 + k4];
            zacc[r].x = fmaf(a.x,w0.x, fmaf(a.y,w1.x, fmaf(a.z,w2.x, fmaf(a.w,w3.x, zacc[r].x))));
            zacc[r].y = fmaf(a.x,w0.y, fmaf(a.y,w1.y, fmaf(a.z,w2.y, fmaf(a.w,w3.y, zacc[r].y))));
        }
    }
    float2 ps = make_float2(0.f,0.f), psq = make_float2(0.f,0.f);
    #pragma unroll
    for (int r = 0; r < 8; r++) {
        int node = nodeBase + r0 + r;
        if (node < n) {
            ((float2*)(z + (size_t)node*64))[lane] = zacc[r];
            ps.x += zacc[r].x; ps.y += zacc[r].y;
            psq.x += zacc[r].x*zacc[r].x; psq.y += zacc[r].y*zacc[r].y;
        }
    }
    atomicAdd(&sSum[2*lane],   ps.x); atomicAdd(&sSum[2*lane+1], ps.y);
    atomicAdd(&sSq [2*lane],   psq.x); atomicAdd(&sSq [2*lane+1], psq.y);
    __syncthreads();
    if (t < 64) { atomicAdd(&stats[t], sSum[t]); atomicAdd(&stats[64+t], sSq[t]); }
}

// ---------------- classifier tail ----------------
__global__ void cls_final_kernel(const float* __restrict__ z, const float* __restrict__ stats,
                                 const float* __restrict__ bng, const float* __restrict__ bnb,
                                 const float* __restrict__ W2, const float* __restrict__ b2,
                                 float* __restrict__ out, int n) {
    __shared__ float sW2[640];
    __shared__ float sb2[16];
    __shared__ float sZ[8][64];
    int t = threadIdx.x, lane = t & 31, warp = t >> 5;
    for (int j = t; j < 640; j += 256) sW2[j] = W2[j];
    if (t < 10) sb2[t] = b2[t];
    __syncthreads();

    float invN = 1.f / (float)n;
    int c0 = 2*lane, c1 = c0 + 1;
    float mu0 = stats[c0]*invN, mu1 = stats[c1]*invN;
    float v0 = stats[64+c0]*invN - mu0*mu0;
    float v1 = stats[64+c1]*invN - mu1*mu1;
    float sc0 = bng[c0] / sqrtf(v0 + EPSV);
    float sc1 = bng[c1] / sqrtf(v1 + EPSV);
    float sh0 = bnb[c0] - mu0*sc0;
    float sh1 = bnb[c1] - mu1*sc1;

    for (int it = 0; it < 8; it++) {
        int row = blockIdx.x*64 + warp*8 + it;
        if (row < n) {
            float2 zv = ((const float2*)(z + (size_t)row*64))[lane];
            sZ[warp][c0] = fmaxf(zv.x*sc0 + sh0, 0.f);
            sZ[warp][c1] = fmaxf(zv.y*sc1 + sh1, 0.f);
            __syncwarp();
            float logit = -1e30f;
            if (lane < 10) {
                logit = sb2[lane];
                #pragma unroll 8
                for (int k = 0; k < 64; k++) logit = fmaf(sZ[warp][k], sW2[k*10+lane], logit);
            }
            float mx = logit;
            #pragma unroll
            for (int m = 16; m >= 1; m >>= 1) mx = fmaxf(mx, __shfl_xor_sync(0xffffffffu, mx, m));
            float ex = (lane < 10) ? expf(logit - mx) : 0.f;
            float s = ex;
            #pragma unroll
            for (int m = 16; m >= 1; m >>= 1) s += __shfl_xor_sync(0xffffffffu, s, m);
            if (lane < 10) out[(size_t)row*10 + lane] = logit - mx - logf(s);
            __syncwarp();
        }
    }
}

// ---------------- host ----------------
extern "C" void kernel_launch(void* const* d_in, const int* in_sizes, int n_in,
                              void* d_out, int out_size) {
    const float* node_features = (const float*)d_in[0];
    const int*   node_ei       = (const int*)d_in[1];
    const float* comm_features = (const float*)d_in[2];
    const int*   comm_ei       = (const int*)d_in[3];
    const int*   n2c           = (const int*)d_in[4];
    const float* node_W   = (const float*)d_in[5];
    const float* node_b   = (const float*)d_in[6];
    const float* node_g   = (const float*)d_in[7];
    const float* node_be  = (const float*)d_in[8];
    const float* comm_W   = (const float*)d_in[9];
    const float* comm_b   = (const float*)d_in[10];
    const float* comm_g   = (const float*)d_in[11];
    const float* comm_be  = (const float*)d_in[12];
    const float* attn_in_w  = (const float*)d_in[13];
    const float* attn_in_b  = (const float*)d_in[14];
    const float* attn_out_w = (const float*)d_in[15];
    const float* attn_out_b = (const float*)d_in[16];
    const float* ln_g  = (const float*)d_in[17];
    const float* ln_b  = (const float*)d_in[18];
    const float* cls_W1 = (const float*)d_in[19];
    const float* cls_b1 = (const float*)d_in[20];
    const float* cls_bg = (const float*)d_in[21];
    const float* cls_bb = (const float*)d_in[22];
    const float* cls_W2 = (const float*)d_in[23];
    const float* cls_b2 = (const float*)d_in[24];
    float* out = (float*)d_out;

    float *bufA, *bufB, *agg, *tmp, *cA, *cB, *cagg, *ctmp, *qkvN, *qkvC, *z1;
    float *stats, *WiT, *WoT;
    cudaGetSymbolAddress((void**)&bufA, g_bufA);
    cudaGetSymbolAddress((void**)&bufB, g_bufB);
    cudaGetSymbolAddress((void**)&agg,  g_agg);
    cudaGetSymbolAddress((void**)&tmp,  g_tmp);
    cudaGetSymbolAddress((void**)&cA,   g_cA);
    cudaGetSymbolAddress((void**)&cB,   g_cB);
    cudaGetSymbolAddress((void**)&cagg, g_cagg);
    cudaGetSymbolAddress((void**)&ctmp, g_ctmp);
    cudaGetSymbolAddress((void**)&qkvN, g_qkvN);
    cudaGetSymbolAddress((void**)&qkvC, g_qkvC);
    cudaGetSymbolAddress((void**)&z1,   g_z1);
    cudaGetSymbolAddress((void**)&stats, g_stats);
    cudaGetSymbolAddress((void**)&WiT,  g_WiT);
    cudaGetSymbolAddress((void**)&WoT,  g_WoT);

    cudaFuncSetAttribute(gemm2_kernel<true>,  cudaFuncAttributeMaxDynamicSharedMemorySize, 98304);
    cudaFuncSetAttribute(gemm2_kernel<false>, cudaFuncAttributeMaxDynamicSharedMemorySize, 98304);
    cudaFuncSetAttribute(attn_cls_kernel,     cudaFuncAttributeMaxDynamicSharedMemorySize, 98816);

    // ---- fused graph prep ----
    zero_transpose_kernel<<<(NN+255)/256, 256>>>(attn_in_w, attn_out_w);
    count_deg2_kernel<<<NBEN + NBEC, 256>>>(node_ei + NE, comm_ei + CE);
    scan_fused_kernel<<<NBN + NBC, 256>>>();
    fill_csr2_kernel<<<NBEN + NBEC, 256>>>(node_ei, node_ei + NE, comm_ei, comm_ei + CE);

    // ---- fused GCN stacks ----
    const float* hinN = node_features;
    const float* hinC = comm_features;
    float* houtsN[3] = { bufA, bufB, bufA };
    float* houtsC[3] = { cA, cB, cA };
    int aggWarps = NN + NC;
    for (int i = 0; i < 3; i++) {
        gcn_agg2_kernel<<<(aggWarps*32 + 255)/256, 256>>>(hinN, agg, hinC, cagg);
        gemm2_kernel<true><<<dim3(GN + GC, 1), 256, 98304>>>(
            agg,  node_W + i*16384, node_b + i*128, tmp,  stats + i*256,     NN,
            cagg, comm_W + i*16384, comm_b + i*128, ctmp, stats + (3+i)*256, NC,
            128, 128);
        bn2_kernel<<<((NN+NC)*32 + 255)/256, 256>>>(
            tmp,  stats + i*256,     node_g + i*128, node_be + i*128, hinN, houtsN[i],
            ctmp, stats + (3+i)*256, comm_g + i*128, comm_be + i*128, hinC, houtsC[i],
            i > 0);
        hinN = houtsN[i];
        hinC = houtsC[i];
    }

    // ---- fused qkv GEMM (3 parallel column-tile blocks) ----
    gemm2_kernel<false><<<dim3(GN + GC, 3), 256, 98304>>>(
        hinN, WiT, attn_in_b, qkvN, nullptr, NN,
        hinC, WiT, attn_in_b, qkvC, nullptr, NC,
        384, 384);

    // ---- attention + LN + cls GEMM1 (phase-structured) ----
    attn_cls_kernel<<<(NN+63)/64, 256, 98816>>>(
        qkvN, qkvC, n2c, hinN, WoT, attn_out_b, ln_g, ln_b,
        cls_W1, cls_b1, z1, stats + 6*256, NN);

    // ---- classifier tail ----
    cls_final_kernel<<<(NN+63)/64, 256>>>(z1, stats + 6*256, cls_bg, cls_bb, cls_W2, cls_b2, out, NN);
}